// round 2
// baseline (speedup 1.0000x reference)
#include <cuda_runtime.h>
#include <math.h>

// Problem shape (fixed by the reference): B=4, H=16, S=2048, DK=128
#define S_LEN   2048
#define D_HEAD  128
#define BH      64
#define ROWS    16       // query rows per CTA (2 rows per warp)
#define KCH     64       // K/V rows staged in smem per chunk
#define KSTRIDE 132      // row stride (floats) -> conflict-free LDS.128
#define NTHREADS 256

// smem (floats): Qs[ROWS*D] + Ks[KCH*KSTRIDE] + Sc[ROWS*S]
#define SMEM_FLOATS (ROWS * D_HEAD + KCH * KSTRIDE + ROWS * S_LEN)

__global__ __launch_bounds__(NTHREADS, 1)
void sdpa_causal_kernel(const float* __restrict__ Q,
                        const float* __restrict__ K,
                        const float* __restrict__ V,
                        float* __restrict__ ctx_out,
                        float* __restrict__ attn_out) {
    extern __shared__ float sm[];
    float* Qs = sm;                         // ROWS * D_HEAD
    float* Ks = sm + ROWS * D_HEAD;         // KCH * KSTRIDE (reused for V)
    float* Sc = Ks + KCH * KSTRIDE;         // ROWS * S_LEN

    const int tid  = threadIdx.x;
    const int warp = tid >> 5;
    const int lane = tid & 31;
    const int bh   = blockIdx.y;
    // heavy causal tiles first (large q0 scheduled early)
    const int q0   = (gridDim.x - 1 - blockIdx.x) * ROWS;

    const size_t base = (size_t)bh * S_LEN;
    const float* Qg = Q + (base + q0) * D_HEAD;
    const float* Kg = K + base * D_HEAD;
    const float* Vg = V + base * D_HEAD;

    // ---- load Q tile (rows contiguous in gmem) ----
    for (int i = tid; i < ROWS * D_HEAD; i += NTHREADS) Qs[i] = Qg[i];

    const int   kend  = q0 + ROWS;               // exclusive bound on needed keys
    const float scale = 0.088388347648318447f;   // 1/sqrt(128)
    const int   r0   = warp * 2;                 // this warp's first query row
    const int   qA   = q0 + r0;                  // global query indices
    const int   qB   = qA + 1;
    float* srow0 = &Sc[r0 * S_LEN];
    float* srow1 = srow0 + S_LEN;

    // ---- Phase B: scores = Q K^T * scale (causal-masked) ----
    // Each warp: 2 query rows x 2 keys per lane -> 4 float4 accumulators.
    for (int kb = 0; kb < kend; kb += KCH) {
        __syncthreads();
        // stage K chunk [kb, kb+KCH) as float4, conflict-free stride
        for (int i = tid; i < KCH * (D_HEAD / 4); i += NTHREADS) {
            int kr = i >> 5, c = i & 31;
            *(float4*)&Ks[kr * KSTRIDE + 4 * c] =
                *(const float4*)&Kg[(size_t)(kb + kr) * D_HEAD + 4 * c];
        }
        __syncthreads();

        float4 a00 = make_float4(0.f, 0.f, 0.f, 0.f);  // rowA x key(lane)
        float4 a01 = make_float4(0.f, 0.f, 0.f, 0.f);  // rowA x key(lane+32)
        float4 a10 = make_float4(0.f, 0.f, 0.f, 0.f);  // rowB x key(lane)
        float4 a11 = make_float4(0.f, 0.f, 0.f, 0.f);  // rowB x key(lane+32)
        const float* qr0 = &Qs[r0 * D_HEAD];
        const float* qr1 = qr0 + D_HEAD;
        const float* k0p = &Ks[lane * KSTRIDE];
        const float* k1p = &Ks[(lane + 32) * KSTRIDE];
        #pragma unroll
        for (int d = 0; d < D_HEAD; d += 4) {
            float4 qa = *(const float4*)&qr0[d];   // broadcast
            float4 qb = *(const float4*)&qr1[d];   // broadcast
            float4 ka = *(const float4*)&k0p[d];
            float4 kk = *(const float4*)&k1p[d];
            a00.x += qa.x * ka.x; a00.y += qa.y * ka.y;
            a00.z += qa.z * ka.z; a00.w += qa.w * ka.w;
            a01.x += qa.x * kk.x; a01.y += qa.y * kk.y;
            a01.z += qa.z * kk.z; a01.w += qa.w * kk.w;
            a10.x += qb.x * ka.x; a10.y += qb.y * ka.y;
            a10.z += qb.z * ka.z; a10.w += qb.w * ka.w;
            a11.x += qb.x * kk.x; a11.y += qb.y * kk.y;
            a11.z += qb.z * kk.z; a11.w += qb.w * kk.w;
        }
        float s00 = (a00.x + a00.y) + (a00.z + a00.w);
        float s01 = (a01.x + a01.y) + (a01.z + a01.w);
        float s10 = (a10.x + a10.y) + (a10.z + a10.w);
        float s11 = (a11.x + a11.y) + (a11.z + a11.w);

        int k0i = kb + lane, k1i = k0i + 32;
        srow0[k0i] = (k0i <= qA) ? s00 * scale : -1e30f;
        srow0[k1i] = (k1i <= qA) ? s01 * scale : -1e30f;
        srow1[k0i] = (k0i <= qB) ? s10 * scale : -1e30f;
        srow1[k1i] = (k1i <= qB) ? s11 * scale : -1e30f;
    }
    // Each lane reads back only entries it wrote (k ≡ lane mod 32): no cross-lane
    // dependency until Phase D, which is fenced by its staging __syncthreads.

    // ---- Phase C: softmax per row + write attn (2 rows per warp) ----
    #pragma unroll
    for (int rr = 0; rr < 2; rr++) {
        float* srow = rr ? srow1 : srow0;
        const int q  = q0 + r0 + rr;
        const int n  = q + 1;  // valid keys

        float m = -INFINITY;
        for (int k = lane; k < n; k += 32) m = fmaxf(m, srow[k]);
        #pragma unroll
        for (int o = 16; o; o >>= 1) m = fmaxf(m, __shfl_xor_sync(0xffffffffu, m, o));

        float l = 0.f;
        for (int k = lane; k < n; k += 32) {
            float e = __expf(srow[k] - m);
            srow[k] = e;
            l += e;
        }
        #pragma unroll
        for (int o = 16; o; o >>= 1) l += __shfl_xor_sync(0xffffffffu, l, o);
        const float inv = 1.0f / l;

        float* arow = attn_out ? (attn_out + (base + q) * (size_t)S_LEN) : (float*)0;
        for (int k = lane; k < S_LEN; k += 32) {
            float pn = (k < n) ? srow[k] * inv : 0.f;
            if (k < kend) srow[k] = pn;     // zero-pad masked region for Phase D
            if (arow) arow[k] = pn;
        }
    }

    // ---- Phase D: context = attn @ V (2 rows per warp) ----
    float4 acc0 = make_float4(0.f, 0.f, 0.f, 0.f);
    float4 acc1 = make_float4(0.f, 0.f, 0.f, 0.f);
    for (int kb = 0; kb < kend; kb += KCH) {
        __syncthreads();
        for (int i = tid; i < KCH * (D_HEAD / 4); i += NTHREADS) {
            int kr = i >> 5, c = i & 31;
            *(float4*)&Ks[kr * KSTRIDE + 4 * c] =
                *(const float4*)&Vg[(size_t)(kb + kr) * D_HEAD + 4 * c];
        }
        __syncthreads();

        const int kmax = min(KCH, kend - kb);
        const float* p0 = &srow0[kb];
        const float* p1 = &srow1[kb];
        #pragma unroll 4
        for (int kk = 0; kk < kmax; kk++) {
            float  pa = p0[kk];                                    // broadcast
            float  pb = p1[kk];                                    // broadcast
            float4 v  = *(const float4*)&Ks[kk * KSTRIDE + 4 * lane];
            acc0.x += pa * v.x; acc0.y += pa * v.y;
            acc0.z += pa * v.z; acc0.w += pa * v.w;
            acc1.x += pb * v.x; acc1.y += pb * v.y;
            acc1.z += pb * v.z; acc1.w += pb * v.w;
        }
    }
    if (ctx_out) {
        *(float4*)&ctx_out[(base + qA) * (size_t)D_HEAD + 4 * lane] = acc0;
        *(float4*)&ctx_out[(base + qB) * (size_t)D_HEAD + 4 * lane] = acc1;
    }
}

extern "C" void kernel_launch(void* const* d_in, const int* in_sizes, int n_in,
                              void* d_out, int out_size) {
    const float* Q = (const float*)d_in[0];
    const float* K = (const float*)d_in[1];
    const float* V = (const float*)d_in[2];
    float* out = (float*)d_out;

    const long long CTX = (long long)BH * S_LEN * D_HEAD;   // 16,777,216
    const long long ATT = (long long)BH * S_LEN * S_LEN;    // 268,435,456

    float* ctx  = 0;
    float* attn = 0;
    if ((long long)out_size == CTX + ATT) { ctx = out; attn = out + CTX; }
    else if ((long long)out_size == CTX)  { ctx = out; }
    else if ((long long)out_size == ATT)  { attn = out; }
    else                                  { ctx = out; }    // fallback

    const size_t smem = (size_t)SMEM_FLOATS * sizeof(float);  // 173,056 B
    cudaFuncSetAttribute(sdpa_causal_kernel,
                         cudaFuncAttributeMaxDynamicSharedMemorySize, (int)smem);

    dim3 grid(S_LEN / ROWS, BH);
    sdpa_causal_kernel<<<grid, NTHREADS, smem>>>(Q, K, V, ctx, attn);
}

// round 16
// speedup vs baseline: 3.5156x; 3.5156x over previous
#include <cuda_runtime.h>
#include <cuda_bf16.h>
#include <math.h>
#include <stdint.h>

// Shape: B=4, H=16 -> BH=64, S=2048, D=128. fp32 in/out.
#define S_LEN    2048
#define D_HEAD   128
#define BH       64
#define TM       128                    // query rows per CTA
#define TN       128                    // keys per k-tile
#define NTHREADS 256                    // 8 warps x 16 rows
#define SCALE    0.088388347648318447f  // 1/sqrt(128)

#define SK       136                    // smem row stride in bf16 (272 B = 17x16B)
#define TILE_B   (128 * SK * 2)         // 34816 B per tile buffer
#define OFF_QHI  0
#define OFF_QLO  (TILE_B)
#define OFF_KHI  (2 * TILE_B)           // reused for V (row-major) in pass 2
#define OFF_KLO  (3 * TILE_B)
#define SM_TOTAL (4 * TILE_B)           // 139264 B

__device__ __forceinline__ uint32_t smem_u32(const void* p) {
    uint32_t a;
    asm("{ .reg .u64 t; cvta.to.shared.u64 t, %1; cvt.u32.u64 %0, t; }"
        : "=r"(a) : "l"(p));
    return a;
}
__device__ __forceinline__ void ldmx4(uint32_t* r, uint32_t a) {
    asm volatile("ldmatrix.sync.aligned.m8n8.x4.shared.b16 {%0,%1,%2,%3}, [%4];"
                 : "=r"(r[0]), "=r"(r[1]), "=r"(r[2]), "=r"(r[3]) : "r"(a));
}
__device__ __forceinline__ void ldmx2(uint32_t* r, uint32_t a) {
    asm volatile("ldmatrix.sync.aligned.m8n8.x2.shared.b16 {%0,%1}, [%2];"
                 : "=r"(r[0]), "=r"(r[1]) : "r"(a));
}
// transposed variant: storing [k][n] + trans-load == storing [n][k] + normal load
__device__ __forceinline__ void ldmx2t(uint32_t* r, uint32_t a) {
    asm volatile("ldmatrix.sync.aligned.m8n8.x2.trans.shared.b16 {%0,%1}, [%2];"
                 : "=r"(r[0]), "=r"(r[1]) : "r"(a));
}
__device__ __forceinline__ void mma_bf16(float* c, const uint32_t* a, const uint32_t* b) {
    asm volatile("mma.sync.aligned.m16n8k16.row.col.f32.bf16.bf16.f32 "
                 "{%0,%1,%2,%3}, {%4,%5,%6,%7}, {%8,%9}, {%0,%1,%2,%3};"
                 : "+f"(c[0]), "+f"(c[1]), "+f"(c[2]), "+f"(c[3])
                 : "r"(a[0]), "r"(a[1]), "r"(a[2]), "r"(a[3]), "r"(b[0]), "r"(b[1]));
}
__device__ __forceinline__ uint32_t pk_bf2(float lo, float hi) {
    __nv_bfloat162 t = __floats2bfloat162_rn(lo, hi);   // .x = lo (low half)
    return *reinterpret_cast<uint32_t*>(&t);
}
__device__ __forceinline__ float bf_hi(float v) {
    return __bfloat162float(__float2bfloat16(v));
}

// fp32 [128x128] row-major -> hi/lo bf16 smem, row-major [row][d], stride SK
// (used for K tiles AND V tiles; V is trans-loaded at the MMA instead)
__device__ __forceinline__ void cvt_tile(char* smem, const float* __restrict__ g, int tid) {
    const float4* g4 = (const float4*)g;
    for (int idx = tid; idx < 128 * 32; idx += NTHREADS) {
        int row = idx >> 5, c4 = (idx & 31) << 2;
        float4 v = g4[idx];
        float hx = bf_hi(v.x), hy = bf_hi(v.y), hz = bf_hi(v.z), hw = bf_hi(v.w);
        uint2 hu = { pk_bf2(hx, hy), pk_bf2(hz, hw) };
        uint2 lu = { pk_bf2(v.x - hx, v.y - hy), pk_bf2(v.z - hz, v.w - hw) };
        int boff = (row * SK + c4) * 2;
        *(uint2*)(smem + OFF_KHI + boff) = hu;
        *(uint2*)(smem + OFF_KLO + boff) = lu;
    }
}
// Q variant (different destination buffers)
__device__ __forceinline__ void cvt_q(char* smem, const float* __restrict__ g, int tid) {
    const float4* g4 = (const float4*)g;
    for (int idx = tid; idx < 128 * 32; idx += NTHREADS) {
        int row = idx >> 5, c4 = (idx & 31) << 2;
        float4 v = g4[idx];
        float hx = bf_hi(v.x), hy = bf_hi(v.y), hz = bf_hi(v.z), hw = bf_hi(v.w);
        uint2 hu = { pk_bf2(hx, hy), pk_bf2(hz, hw) };
        uint2 lu = { pk_bf2(v.x - hx, v.y - hy), pk_bf2(v.z - hz, v.w - hw) };
        int boff = (row * SK + c4) * 2;
        *(uint2*)(smem + OFF_QHI + boff) = hu;
        *(uint2*)(smem + OFF_QLO + boff) = lu;
    }
}

__global__ __launch_bounds__(NTHREADS, 1)
void sdpa_mma_kernel(const float* __restrict__ Q,
                     const float* __restrict__ K,
                     const float* __restrict__ V,
                     float* __restrict__ ctx_out,
                     float* __restrict__ attn_out) {
    extern __shared__ char smem[];
    const uint32_t sb = smem_u32(smem);
    const int tid = threadIdx.x;
    const int w   = tid >> 5;
    const int l   = tid & 31;
    const int bh  = blockIdx.y;
    const int qt  = gridDim.x - 1 - blockIdx.x;   // heavy tiles first
    const int q0  = qt * TM;
    const int kend = q0 + TM;

    const size_t base = (size_t)bh * S_LEN;
    const float* Qg = Q + (base + q0) * D_HEAD;
    const float* Kg = K + base * D_HEAD;
    const float* Vg = V + base * D_HEAD;

    // lane-derived fragment geometry
    const int lr     = l & 7;
    const int grp    = l >> 3;
    const int a_row  = w * 16 + lr + (grp & 1) * 8;  // Q ldmatrix.x4 row
    const int a_colg = (grp >> 1) * 8;               // Q ldmatrix.x4 col group
    const int b_lr   = l & 7;                        // B ldmatrix.x2 (lanes 0-15 used)
    const int b_half = (l >> 3) & 1;
    const int qrow   = l >> 2;                       // c-frag row within 8
    const int qcol2  = (l & 3) * 2;                  // c-frag col pair
    const int rA     = w * 16 + qrow;                // local rows of this thread
    const int rB     = rA + 8;

    cvt_q(smem, Qg, tid);

    // zero attn region beyond kend for this CTA's 128 rows
    if (attn_out) {
        const int Lq = (S_LEN - kend) >> 2;
        const int n4 = 128 * Lq;
        float4 z = make_float4(0.f, 0.f, 0.f, 0.f);
        for (int i = tid; i < n4; i += NTHREADS) {
            int r = i / (Lq ? Lq : 1), c = (i % (Lq ? Lq : 1)) << 2;
            *(float4*)&attn_out[(base + q0 + r) * (size_t)S_LEN + kend + c] = z;
        }
    }

    // =================== PASS 1: row sums of exp ===================
    float lsA = 0.f, lsB = 0.f;
    for (int t = 0; t <= qt; t++) {
        __syncthreads();
        cvt_tile(smem, Kg + (size_t)t * TN * D_HEAD, tid);
        __syncthreads();

        float S[16][4];
        #pragma unroll
        for (int nb = 0; nb < 16; nb++) { S[nb][0]=0.f; S[nb][1]=0.f; S[nb][2]=0.f; S[nb][3]=0.f; }

        #pragma unroll
        for (int ks = 0; ks < 8; ks++) {
            uint32_t ah[4], al[4];
            uint32_t qa = sb + OFF_QHI + (uint32_t)(a_row * SK + ks * 16 + a_colg) * 2;
            ldmx4(ah, qa);
            ldmx4(al, qa + (OFF_QLO - OFF_QHI));
            #pragma unroll
            for (int nb = 0; nb < 16; nb++) {
                uint32_t bhr[2], blr[2];
                uint32_t ka = sb + OFF_KHI + (uint32_t)((nb * 8 + b_lr) * SK + ks * 16 + b_half * 8) * 2;
                ldmx2(bhr, ka);
                ldmx2(blr, ka + (OFF_KLO - OFF_KHI));
                mma_bf16(S[nb], ah, bhr);
                mma_bf16(S[nb], al, bhr);
                mma_bf16(S[nb], ah, blr);
            }
        }
        const bool diag = (t == qt);
        #pragma unroll
        for (int nb = 0; nb < 16; nb++) {
            int c0 = nb * 8 + qcol2;
            float e0 = __expf(S[nb][0] * SCALE); if (diag && c0     > rA) e0 = 0.f;
            float e1 = __expf(S[nb][1] * SCALE); if (diag && c0 + 1 > rA) e1 = 0.f;
            float e2 = __expf(S[nb][2] * SCALE); if (diag && c0     > rB) e2 = 0.f;
            float e3 = __expf(S[nb][3] * SCALE); if (diag && c0 + 1 > rB) e3 = 0.f;
            lsA += e0 + e1;
            lsB += e2 + e3;
        }
    }
    lsA += __shfl_xor_sync(0xffffffffu, lsA, 1);
    lsA += __shfl_xor_sync(0xffffffffu, lsA, 2);
    lsB += __shfl_xor_sync(0xffffffffu, lsB, 1);
    lsB += __shfl_xor_sync(0xffffffffu, lsB, 2);
    const float invA = 1.0f / lsA;
    const float invB = 1.0f / lsB;

    // ============ PASS 2: recompute S, write attn, O += P V ============
    float O[16][4];
    #pragma unroll
    for (int db = 0; db < 16; db++) { O[db][0]=0.f; O[db][1]=0.f; O[db][2]=0.f; O[db][3]=0.f; }

    float* arA = attn_out ? attn_out + (base + q0 + rA) * (size_t)S_LEN : (float*)0;
    float* arB = attn_out ? attn_out + (base + q0 + rB) * (size_t)S_LEN : (float*)0;

    for (int t = 0; t <= qt; t++) {
        __syncthreads();   // previous tile's V reads done
        cvt_tile(smem, Kg + (size_t)t * TN * D_HEAD, tid);
        __syncthreads();

        float S[16][4];
        #pragma unroll
        for (int nb = 0; nb < 16; nb++) { S[nb][0]=0.f; S[nb][1]=0.f; S[nb][2]=0.f; S[nb][3]=0.f; }

        #pragma unroll
        for (int ks = 0; ks < 8; ks++) {
            uint32_t ah[4], al[4];
            uint32_t qa = sb + OFF_QHI + (uint32_t)(a_row * SK + ks * 16 + a_colg) * 2;
            ldmx4(ah, qa);
            ldmx4(al, qa + (OFF_QLO - OFF_QHI));
            #pragma unroll
            for (int nb = 0; nb < 16; nb++) {
                uint32_t bhr[2], blr[2];
                uint32_t ka = sb + OFF_KHI + (uint32_t)((nb * 8 + b_lr) * SK + ks * 16 + b_half * 8) * 2;
                ldmx2(bhr, ka);
                ldmx2(blr, ka + (OFF_KLO - OFF_KHI));
                mma_bf16(S[nb], ah, bhr);
                mma_bf16(S[nb], al, bhr);
                mma_bf16(S[nb], ah, blr);
            }
        }

        // normalize, causal mask, write attn, keep P in S regs
        const bool diag = (t == qt);
        #pragma unroll
        for (int nb = 0; nb < 16; nb++) {
            int c0 = nb * 8 + qcol2;
            float p0 = __expf(S[nb][0] * SCALE) * invA; if (diag && c0     > rA) p0 = 0.f;
            float p1 = __expf(S[nb][1] * SCALE) * invA; if (diag && c0 + 1 > rA) p1 = 0.f;
            float p2 = __expf(S[nb][2] * SCALE) * invB; if (diag && c0     > rB) p2 = 0.f;
            float p3 = __expf(S[nb][3] * SCALE) * invB; if (diag && c0 + 1 > rB) p3 = 0.f;
            S[nb][0] = p0; S[nb][1] = p1; S[nb][2] = p2; S[nb][3] = p3;
            if (arA) {
                *(float2*)&arA[t * TN + c0] = make_float2(p0, p1);
                *(float2*)&arB[t * TN + c0] = make_float2(p2, p3);
            }
        }

        __syncthreads();   // all warps done reading K smem
        // V tile stored ROW-MAJOR [key][d] (conflict-free stores);
        // transpose happens in ldmatrix.trans at the MMA below.
        cvt_tile(smem, Vg + (size_t)t * TN * D_HEAD, tid);
        __syncthreads();

        // O += P @ V  (A fragments straight from S registers, 3-split)
        #pragma unroll
        for (int kc = 0; kc < 8; kc++) {
            uint32_t ph[4], pl[4];
            {
                float h00 = bf_hi(S[2*kc][0]),   h01 = bf_hi(S[2*kc][1]);
                float h02 = bf_hi(S[2*kc][2]),   h03 = bf_hi(S[2*kc][3]);
                float h10 = bf_hi(S[2*kc+1][0]), h11 = bf_hi(S[2*kc+1][1]);
                float h12 = bf_hi(S[2*kc+1][2]), h13 = bf_hi(S[2*kc+1][3]);
                ph[0] = pk_bf2(h00, h01); ph[1] = pk_bf2(h02, h03);
                ph[2] = pk_bf2(h10, h11); ph[3] = pk_bf2(h12, h13);
                pl[0] = pk_bf2(S[2*kc][0]-h00,   S[2*kc][1]-h01);
                pl[1] = pk_bf2(S[2*kc][2]-h02,   S[2*kc][3]-h03);
                pl[2] = pk_bf2(S[2*kc+1][0]-h10, S[2*kc+1][1]-h11);
                pl[3] = pk_bf2(S[2*kc+1][2]-h12, S[2*kc+1][3]-h13);
            }
            // trans-load: lanes 0-7 -> key rows kc*16+0..7, lanes 8-15 -> +8;
            // column offset selects d-block db*8.
            const uint32_t vrow = sb + OFF_KHI +
                (uint32_t)((kc * 16 + b_lr + b_half * 8) * SK) * 2;
            #pragma unroll
            for (int db = 0; db < 16; db++) {
                uint32_t bhr[2], blr[2];
                uint32_t va = vrow + (uint32_t)(db * 8) * 2;
                ldmx2t(bhr, va);
                ldmx2t(blr, va + (OFF_KLO - OFF_KHI));
                mma_bf16(O[db], ph, bhr);
                mma_bf16(O[db], pl, bhr);
                mma_bf16(O[db], ph, blr);
            }
        }
    }

    // =================== write context ===================
    if (ctx_out) {
        float* crA = ctx_out + (base + q0 + rA) * (size_t)D_HEAD;
        float* crB = ctx_out + (base + q0 + rB) * (size_t)D_HEAD;
        #pragma unroll
        for (int db = 0; db < 16; db++) {
            *(float2*)&crA[db * 8 + qcol2] = make_float2(O[db][0], O[db][1]);
            *(float2*)&crB[db * 8 + qcol2] = make_float2(O[db][2], O[db][3]);
        }
    }
}

extern "C" void kernel_launch(void* const* d_in, const int* in_sizes, int n_in,
                              void* d_out, int out_size) {
    const float* Q = (const float*)d_in[0];
    const float* K = (const float*)d_in[1];
    const float* V = (const float*)d_in[2];
    float* out = (float*)d_out;

    const long long CTX = (long long)BH * S_LEN * D_HEAD;   // 16,777,216
    const long long ATT = (long long)BH * S_LEN * S_LEN;    // 268,435,456

    float* ctx  = 0;
    float* attn = 0;
    if ((long long)out_size == CTX + ATT) { ctx = out; attn = out + CTX; }
    else if ((long long)out_size == CTX)  { ctx = out; }
    else if ((long long)out_size == ATT)  { attn = out; }
    else                                  { ctx = out; }

    cudaFuncSetAttribute(sdpa_mma_kernel,
                         cudaFuncAttributeMaxDynamicSharedMemorySize, SM_TOTAL);

    dim3 grid(S_LEN / TM, BH);   // 16 x 64
    sdpa_mma_kernel<<<grid, NTHREADS, SM_TOTAL>>>(Q, K, V, ctx, attn);
}